// round 1
// baseline (speedup 1.0000x reference)
#include <cuda_runtime.h>
#include <math.h>

// Problem constants (HFALoss): N=4096 samples, C=1000 classes, A=64 feature dim.
#define NB 4096
#define CC 1000
#define AA 64
#define TPB 256

// Scratch: per-sample NLL (no cudaMalloc allowed -> __device__ global).
__device__ float g_nll[NB];

// Main kernel: one block per sample n.
//  - stage CV_n (64x64 fp32, 16KB) + w_k into shared
//  - each thread handles classes c = tid, tid+256, ... : d = w_c - w_k in regs,
//    sigma2 = d^T CV d via broadcast LDS.128 + FFMA, online softmax (m,s)
//  - block-combine (m,s), capture logit at c = target, NLL -> g_nll[n]
__global__ void __launch_bounds__(TPB) hfa_main_kernel(
    const float* __restrict__ W,      // (C, A)
    const float* __restrict__ Y,      // (N, C)
    const int*   __restrict__ tgt,    // (N,)
    const float* __restrict__ ratio_p,// (1,)
    const float* __restrict__ CV)     // (N, A, A)
{
    const int n   = blockIdx.x;
    const int tid = threadIdx.x;

    __shared__ float4 sM[AA * AA / 4];   // CV_n row-major, float4-packed (16KB)
    __shared__ float  sWk[AA];
    __shared__ float  sm_m[TPB / 32];
    __shared__ float  sm_s[TPB / 32];
    __shared__ float  s_lk;

    const int   k          = tgt[n];
    const float half_ratio = 0.5f * ratio_p[0];

    const float4* CV4 = reinterpret_cast<const float4*>(CV) + (size_t)n * (AA * AA / 4);
    for (int i = tid; i < AA * AA / 4; i += TPB) sM[i] = CV4[i];
    if (tid < AA) sWk[tid] = W[k * AA + tid];
    __syncthreads();

    // ||w_k||^2 (redundant per thread, trivial cost)
    float w2k = 0.f;
    #pragma unroll
    for (int a = 0; a < AA; a++) w2k = fmaf(sWk[a], sWk[a], w2k);

    float m = -INFINITY;   // running max
    float s = 0.f;         // running sum of exp(logit - m)
    float lk = 0.f;
    bool  have_k = false;

    for (int c = tid; c < CC; c += TPB) {
        // load w_c, build d = w_c - w_k in registers, accumulate ||w_c||^2
        float d[AA];
        float w2c = 0.f;
        const float4* wc4 = reinterpret_cast<const float4*>(W + c * AA);
        #pragma unroll
        for (int i = 0; i < AA / 4; i++) {
            float4 w = wc4[i];
            w2c = fmaf(w.x, w.x, w2c);
            w2c = fmaf(w.y, w.y, w2c);
            w2c = fmaf(w.z, w.z, w2c);
            w2c = fmaf(w.w, w.w, w2c);
            d[4 * i + 0] = w.x - sWk[4 * i + 0];
            d[4 * i + 1] = w.y - sWk[4 * i + 1];
            d[4 * i + 2] = w.z - sWk[4 * i + 2];
            d[4 * i + 3] = w.w - sWk[4 * i + 3];
        }

        // sigma2/ratio = sum_a d[a] * (sum_b CV[a][b] * d[b])
        float acc = 0.f;
        #pragma unroll 4
        for (int a = 0; a < AA; a++) {
            float ta = 0.f;
            #pragma unroll
            for (int b = 0; b < AA / 4; b++) {
                float4 mr = sM[a * (AA / 4) + b];   // broadcast LDS.128
                ta = fmaf(mr.x, d[4 * b + 0], ta);
                ta = fmaf(mr.y, d[4 * b + 1], ta);
                ta = fmaf(mr.z, d[4 * b + 2], ta);
                ta = fmaf(mr.w, d[4 * b + 3], ta);
            }
            acc = fmaf(d[a], ta, acc);
        }

        float logit = Y[(size_t)n * CC + c] + fmaf(half_ratio, acc, w2c - w2k);

        // online softmax update
        float nm = fmaxf(m, logit);
        s = s * expf(m - nm) + expf(logit - nm);
        m = nm;
        if (c == k) { lk = logit; have_k = true; }
    }

    if (have_k) s_lk = lk;   // exactly one thread in the block hits c == k

    // warp-level (m,s) merge
    #pragma unroll
    for (int off = 16; off > 0; off >>= 1) {
        float mo = __shfl_xor_sync(0xffffffffu, m, off);
        float so = __shfl_xor_sync(0xffffffffu, s, off);
        float nm = fmaxf(m, mo);
        s = s * expf(m - nm) + so * expf(mo - nm);
        m = nm;
    }
    if ((tid & 31) == 0) { sm_m[tid >> 5] = m; sm_s[tid >> 5] = s; }
    __syncthreads();

    if (tid == 0) {
        float M = sm_m[0], S = sm_s[0];
        #pragma unroll
        for (int w = 1; w < TPB / 32; w++) {
            float mo = sm_m[w], so = sm_s[w];
            float nm = fmaxf(M, mo);
            S = S * expf(M - nm) + so * expf(mo - nm);
            M = nm;
        }
        // NLL_n = logsumexp(logits) - logit_target
        g_nll[n] = (M + logf(S)) - s_lk;
    }
}

// Deterministic fixed-order mean of g_nll -> out[0].
__global__ void __launch_bounds__(TPB) hfa_finalize_kernel(float* __restrict__ out)
{
    __shared__ float sh[TPB];
    float acc = 0.f;
    for (int i = threadIdx.x; i < NB; i += TPB) acc += g_nll[i];
    sh[threadIdx.x] = acc;
    __syncthreads();
    #pragma unroll
    for (int off = TPB / 2; off > 0; off >>= 1) {
        if (threadIdx.x < off) sh[threadIdx.x] += sh[threadIdx.x + off];
        __syncthreads();
    }
    if (threadIdx.x == 0) out[0] = sh[0] * (1.0f / NB);
}

extern "C" void kernel_launch(void* const* d_in, const int* in_sizes, int n_in,
                              void* d_out, int out_size)
{
    // metadata order: weight_m, y, features, target_x, ratio, final_conv, class_num
    const float* W     = (const float*)d_in[0];
    const float* Y     = (const float*)d_in[1];
    // d_in[2] = features (unused by the reference math)
    const int*   tgt   = (const int*)  d_in[3];
    const float* ratio = (const float*)d_in[4];
    const float* CV    = (const float*)d_in[5];

    float* out = (float*)d_out;

    hfa_main_kernel<<<NB, TPB>>>(W, Y, tgt, ratio, CV);
    hfa_finalize_kernel<<<1, TPB>>>(out);

    // Second output: y passthrough, concatenated after the scalar loss.
    if (out_size >= 1 + NB * CC) {
        cudaMemcpyAsync(out + 1, Y, (size_t)NB * CC * sizeof(float),
                        cudaMemcpyDeviceToDevice, 0);
    } else if (out_size == NB * CC) {
        // fallback layout: y only
        cudaMemcpyAsync(out, Y, (size_t)NB * CC * sizeof(float),
                        cudaMemcpyDeviceToDevice, 0);
    }
}

// round 4
// speedup vs baseline: 6.7447x; 6.7447x over previous
#include <cuda_runtime.h>
#include <math.h>
#include <stdint.h>

// HFALoss: N=4096, C=1000 (pad 1024), A=64.
// logits = y + 0.5*ratio*(d^T CV d) + ||w_c||^2 - ||w_k||^2,  d = w_c - w_k
// Reformulated:  d^T CV d = q_cc - w_c.u_n + r_n   with
//   q_cc    = sum_{a<=b} packA[n,ab] * packG[c,ab]   (sym-packed, K1=2080)
//   cross   = tail K2=64:  A tail = -(CV+CV^T)w_k,  G tail = w_c
//   r_n     = w_k^T CV w_k  (folded into row const)
// => one dense tf32 GEMM: Q[4096 x 1024] = Apack[4096 x 2144] @ Gpack^T.
#define NB    4096
#define CC    1000
#define CPAD  1024
#define AA    64
#define KTRI  2080            // 64*65/2
#define KP    2144            // KTRI + 64, = 67 * 32 exactly
#define KT    67
#define BM    128
#define BN    128
#define BK    32
#define STAGES 4
#define PITCH 36              // floats per smem row (32 data + 4 pad)
#define STAGE_BYTES (2 * BM * PITCH * 4)      // A tile + B tile = 36864
#define SMEM_TOTAL  (STAGES * STAGE_BYTES)    // 147456

// ---------------- device scratch (no cudaMalloc allowed) ----------------
__device__ __align__(128) float g_A[(size_t)NB * KP];       // 35.1 MB
__device__ __align__(128) float g_B[(size_t)CPAD * KP];     //  8.8 MB
__device__ __align__(128) float g_logits[(size_t)NB * CC];  // 16.4 MB
__device__ float  g_rowconst[NB];
__device__ float  g_w2[CPAD];
__device__ float  g_nll[NB];
__device__ ushort2 g_map[KTRI];     // idx -> (a,b), a<=b

__device__ __forceinline__ float tf32r(float x) {
    uint32_t u;
    asm("cvt.rna.tf32.f32 %0, %1;" : "=r"(u) : "f"(x));
    return __uint_as_float(u);
}
__device__ __forceinline__ void cpasync16(uint32_t s, const void* g) {
    asm volatile("cp.async.cg.shared.global [%0], [%1], 16;\n" :: "r"(s), "l"(g));
}
__device__ __forceinline__ uint32_t smem_u32(const void* p) {
    uint32_t a;
    asm("{ .reg .u64 t; cvta.to.shared.u64 t, %1; cvt.u32.u64 %0, t; }" : "=r"(a) : "l"(p));
    return a;
}
__device__ __forceinline__ void mma_tf32(float* c, const float* a, const float* b) {
    asm volatile(
        "mma.sync.aligned.m16n8k8.row.col.f32.tf32.tf32.f32 "
        "{%0,%1,%2,%3}, {%4,%5,%6,%7}, {%8,%9}, {%0,%1,%2,%3};"
        : "+f"(c[0]), "+f"(c[1]), "+f"(c[2]), "+f"(c[3])
        : "f"(a[0]), "f"(a[1]), "f"(a[2]), "f"(a[3]), "f"(b[0]), "f"(b[1]));
}

// ---------------- map init: idx -> (a,b) ----------------
__global__ void map_kernel() {
    int a = threadIdx.x;                       // 64 threads
    int base = 64 * a - (a * (a - 1)) / 2;
    for (int b = a; b < AA; b++) g_map[base + (b - a)] = make_ushort2((unsigned short)a, (unsigned short)b);
}

// ---------------- Gpack: per class c ----------------
__global__ void __launch_bounds__(256) prep_G_kernel(const float* __restrict__ W)
{
    __shared__ float sw[AA];
    const int c = blockIdx.x, tid = threadIdx.x;
    const bool valid = (c < CC);
    if (tid < AA) sw[tid] = valid ? W[c * AA + tid] : 0.f;
    __syncthreads();
    if (tid == 0) {
        float s = 0.f;
        #pragma unroll
        for (int a = 0; a < AA; a++) s = fmaf(sw[a], sw[a], s);
        g_w2[c] = s;
    }
    float* row = g_B + (size_t)c * KP;
    for (int t = tid; t < KP; t += 256) {
        float v;
        if (t < KTRI) { ushort2 ab = g_map[t]; v = sw[ab.x] * sw[ab.y]; }
        else          { v = sw[t - KTRI]; }
        row[t] = tf32r(v);
    }
}

// ---------------- Apack + row consts: per sample n ----------------
__global__ void __launch_bounds__(256) prep_A_kernel(
    const float* __restrict__ W, const int* __restrict__ tgt,
    const float* __restrict__ ratio_p, const float* __restrict__ CV)
{
    __shared__ float sM[AA * 65];
    __shared__ float swk[AA];
    __shared__ float su[AA];
    __shared__ float red[AA], red2[AA];
    const int n = blockIdx.x, tid = threadIdx.x;
    const int k = tgt[n];

    const float4* cv4 = reinterpret_cast<const float4*>(CV + (size_t)n * AA * AA);
    for (int i = 0; i < 4; i++) {
        int idx4 = tid + i * 256;              // 0..1023
        float4 v = cv4[idx4];
        int row = idx4 >> 4, c0 = (idx4 & 15) * 4;
        float* d = sM + row * 65 + c0;
        d[0] = v.x; d[1] = v.y; d[2] = v.z; d[3] = v.w;
    }
    if (tid < AA) swk[tid] = W[k * AA + tid];
    __syncthreads();

    if (tid < AA) {
        const int a = tid;
        float trow = 0.f, tcol = 0.f;
        #pragma unroll 8
        for (int b = 0; b < AA; b++) {
            float wb = swk[b];
            trow = fmaf(sM[a * 65 + b], wb, trow);
            tcol = fmaf(sM[b * 65 + a], wb, tcol);
        }
        su[a]   = trow + tcol;          // ((CV+CV^T) w_k)[a]
        red[a]  = swk[a] * trow;        // -> w_k^T CV w_k
        red2[a] = swk[a] * swk[a];      // -> ||w_k||^2
    }
    __syncthreads();
    for (int off = 32; off > 0; off >>= 1) {
        if (tid < off) { red[tid] += red[tid + off]; red2[tid] += red2[tid + off]; }
        __syncthreads();
    }
    if (tid == 0) g_rowconst[n] = fmaf(0.5f * ratio_p[0], red[0], -red2[0]);

    float* row = g_A + (size_t)n * KP;
    for (int t = tid; t < KP; t += 256) {
        float v;
        if (t < KTRI) {
            ushort2 ab = g_map[t];
            v = (ab.x == ab.y) ? sM[ab.x * 65 + ab.x]
                               : sM[ab.x * 65 + ab.y] + sM[ab.y * 65 + ab.x];
        } else {
            v = -su[t - KTRI];
        }
        row[t] = tf32r(v);
    }
}

// ---------------- GEMM + epilogue ----------------
__global__ void __launch_bounds__(256, 1) gemm_kernel(const float* __restrict__ ratio_p)
{
    extern __shared__ char smem[];
    const uint32_t sbase = smem_u32(smem);
    const int tid  = threadIdx.x;
    const int wid  = tid >> 5;
    const int lane = tid & 31;
    const int gid  = lane >> 2;       // 0..7
    const int tig  = lane & 3;        // 0..3
    const int m0 = blockIdx.x * BM;
    const int c0 = blockIdx.y * BN;
    const int wm0 = (wid >> 2) * 64;  // 0, 64
    const int wn0 = (wid & 3) * 32;   // 0,32,64,96

    float acc[4][4][4];
    #pragma unroll
    for (int i = 0; i < 4; i++)
        #pragma unroll
        for (int j = 0; j < 4; j++)
            #pragma unroll
            for (int r = 0; r < 4; r++) acc[i][j][r] = 0.f;

    auto fill = [&](int s, int kt) {
        uint32_t base = sbase + s * STAGE_BYTES;
        #pragma unroll
        for (int i = 0; i < 4; i++) {
            int ch = tid + i * 256;            // 0..1023
            int row = ch >> 3, cc = ch & 7;
            cpasync16(base + row * (PITCH * 4) + cc * 16,
                      g_A + (size_t)(m0 + row) * KP + kt * BK + cc * 4);
        }
        #pragma unroll
        for (int i = 0; i < 4; i++) {
            int ch = tid + i * 256;
            int row = ch >> 3, cc = ch & 7;
            cpasync16(base + BM * (PITCH * 4) + row * (PITCH * 4) + cc * 16,
                      g_B + (size_t)(c0 + row) * KP + kt * BK + cc * 4);
        }
        asm volatile("cp.async.commit_group;\n" ::: "memory");
    };

    #pragma unroll
    for (int p = 0; p < STAGES - 1; p++) fill(p, p);

    for (int kt = 0; kt < KT; kt++) {
        asm volatile("cp.async.wait_group %0;\n" :: "n"(STAGES - 2) : "memory");
        __syncthreads();
        if (kt + STAGES - 1 < KT) fill((kt + STAGES - 1) & 3, kt + STAGES - 1);
        else asm volatile("cp.async.commit_group;\n" ::: "memory");

        const float* sA = reinterpret_cast<const float*>(smem + (kt & 3) * STAGE_BYTES);
        const float* sB = sA + BM * PITCH;
        #pragma unroll
        for (int ks = 0; ks < 4; ks++) {
            const int k0 = ks * 8;
            float af[4][4], bf[4][2];
            #pragma unroll
            for (int mt = 0; mt < 4; mt++) {
                int rb = wm0 + mt * 16 + gid;
                af[mt][0] = sA[rb * PITCH + k0 + tig];
                af[mt][1] = sA[(rb + 8) * PITCH + k0 + tig];
                af[mt][2] = sA[rb * PITCH + k0 + tig + 4];
                af[mt][3] = sA[(rb + 8) * PITCH + k0 + tig + 4];
            }
            #pragma unroll
            for (int nt = 0; nt < 4; nt++) {
                int cb = wn0 + nt * 8 + gid;
                bf[nt][0] = sB[cb * PITCH + k0 + tig];
                bf[nt][1] = sB[cb * PITCH + k0 + tig + 4];
            }
            #pragma unroll
            for (int mt = 0; mt < 4; mt++)
                #pragma unroll
                for (int nt = 0; nt < 4; nt++)
                    mma_tf32(acc[mt][nt], af[mt], bf[nt]);
        }
    }

    // epilogue: logit_partial = hr*acc + rowconst[r] + w2[c]
    const float hr = 0.5f * ratio_p[0];
    #pragma unroll
    for (int mt = 0; mt < 4; mt++) {
        int r0 = m0 + wm0 + mt * 16 + gid;
        int r1 = r0 + 8;
        float rc0 = g_rowconst[r0], rc1 = g_rowconst[r1];
        #pragma unroll
        for (int nt = 0; nt < 4; nt++) {
            int col = c0 + wn0 + nt * 8 + 2 * tig;
            if (col < CC) {
                float w20 = g_w2[col], w21 = g_w2[col + 1];
                float2 v0 = make_float2(fmaf(hr, acc[mt][nt][0], rc0 + w20),
                                        fmaf(hr, acc[mt][nt][1], rc0 + w21));
                float2 v1 = make_float2(fmaf(hr, acc[mt][nt][2], rc1 + w20),
                                        fmaf(hr, acc[mt][nt][3], rc1 + w21));
                *reinterpret_cast<float2*>(&g_logits[(size_t)r0 * CC + col]) = v0;
                *reinterpret_cast<float2*>(&g_logits[(size_t)r1 * CC + col]) = v1;
            }
        }
    }
}

// ---------------- softmax / NLL: one warp per row ----------------
__global__ void __launch_bounds__(256) softmax_kernel(
    const float* __restrict__ Y, const int* __restrict__ tgt)
{
    const int n = blockIdx.x * 8 + (threadIdx.x >> 5);
    const int lane = threadIdx.x & 31;
    const float* Lp = g_logits + (size_t)n * CC;
    const float* Yp = Y + (size_t)n * CC;
    const int k = tgt[n];
    float m = -INFINITY, s = 0.f, lk = 0.f;
    for (int i = lane; i < CC; i += 32) {
        float v = Lp[i] + Yp[i];
        float nm = fmaxf(m, v);
        s = s * expf(m - nm) + expf(v - nm);
        m = nm;
        if (i == k) lk = v;
    }
    lk = __shfl_sync(0xffffffffu, lk, k & 31);
    #pragma unroll
    for (int off = 16; off > 0; off >>= 1) {
        float mo = __shfl_xor_sync(0xffffffffu, m, off);
        float so = __shfl_xor_sync(0xffffffffu, s, off);
        float nm = fmaxf(m, mo);
        s = s * expf(m - nm) + so * expf(mo - nm);
        m = nm;
    }
    if (lane == 0) g_nll[n] = (m + logf(s)) - lk;
}

__global__ void __launch_bounds__(256) finalize_kernel(float* __restrict__ out)
{
    __shared__ float sh[256];
    float acc = 0.f;
    const float4* p = reinterpret_cast<const float4*>(g_nll);
    for (int i = threadIdx.x; i < NB / 4; i += 256) {
        float4 v = p[i];
        acc += (v.x + v.y) + (v.z + v.w);
    }
    sh[threadIdx.x] = acc;
    __syncthreads();
    #pragma unroll
    for (int off = 128; off > 0; off >>= 1) {
        if (threadIdx.x < off) sh[threadIdx.x] += sh[threadIdx.x + off];
        __syncthreads();
    }
    if (threadIdx.x == 0) out[0] = sh[0] * (1.0f / NB);
}

// ---------------- host ----------------
extern "C" void kernel_launch(void* const* d_in, const int* in_sizes, int n_in,
                              void* d_out, int out_size)
{
    const float* W     = (const float*)d_in[0];
    const float* Y     = (const float*)d_in[1];
    const int*   tgt   = (const int*)  d_in[3];
    const float* ratio = (const float*)d_in[4];
    const float* CV    = (const float*)d_in[5];
    float* out = (float*)d_out;

    cudaFuncSetAttribute(gemm_kernel, cudaFuncAttributeMaxDynamicSharedMemorySize, SMEM_TOTAL);

    map_kernel<<<1, 64>>>();
    prep_G_kernel<<<CPAD, 256>>>(W);
    prep_A_kernel<<<NB, 256>>>(W, tgt, ratio, CV);
    gemm_kernel<<<dim3(NB / BM, CPAD / BN), 256, SMEM_TOTAL>>>(ratio);
    softmax_kernel<<<NB / 8, 256>>>(Y, tgt);
    finalize_kernel<<<1, 256>>>(out);

    if (out_size >= 1 + NB * CC) {
        cudaMemcpyAsync(out + 1, Y, (size_t)NB * CC * sizeof(float),
                        cudaMemcpyDeviceToDevice, 0);
    } else if (out_size == NB * CC) {
        cudaMemcpyAsync(out, Y, (size_t)NB * CC * sizeof(float),
                        cudaMemcpyDeviceToDevice, 0);
    }
}

// round 5
// speedup vs baseline: 6.9131x; 1.0250x over previous
#include <cuda_runtime.h>
#include <math.h>
#include <stdint.h>

// HFALoss: N=4096, C=1000 (pad 1024), A=64.
// logits = y + 0.5*ratio*(d^T CV d) + ||w_c||^2 - ||w_k||^2,  d = w_c - w_k
// d^T CV d = q_cc - w_c.u_n + r_n ; q via sym-packed GEMM (K1=2080) + cross tail (64).
// Q[4096x1024] = Apack[4096x2144] @ Gpack^T, tf32 mma.sync m16n8k8.
#define NB    4096
#define CC    1000
#define CPAD  1024
#define AA    64
#define KTRI  2080
#define KP    2144            // 67 * 32
#define KT    67
#define BM    128
#define BN    128
#define BK    32

#define PA    40              // A smem pitch (floats): conflict-free LDS.64
#define A_TILE_B (BM * PA * 4)            // 20480
#define PBR   264             // B smem pitch (floats) per k-pair row: CF LDS.64
#define B_TILE_B (16 * PBR * 4)           // 16896
#define STAGE_B  (A_TILE_B + B_TILE_B)    // 37376
#define STAGES 3
#define SMEM_TOTAL (STAGES * STAGE_B)     // 112128

// ---------------- device scratch ----------------
__device__ __align__(128) float g_A[(size_t)NB * KP];        // row-major, k-pair-permuted
__device__ __align__(128) float g_B[(size_t)KT * 16 * 2048]; // [kt][r=16][c=1024][2]
__device__ __align__(128) float g_logits[(size_t)NB * CC];
__device__ float  g_rowconst[NB];
__device__ float  g_w2[CPAD];
__device__ float  g_nll[NB];
__device__ ushort2 g_map[KTRI];

__device__ __forceinline__ float tf32r(float x) {
    uint32_t u;
    asm("cvt.rna.tf32.f32 %0, %1;" : "=r"(u) : "f"(x));
    return __uint_as_float(u);
}
__device__ __forceinline__ void cpasync16(uint32_t s, const void* g) {
    asm volatile("cp.async.cg.shared.global [%0], [%1], 16;\n" :: "r"(s), "l"(g));
}
__device__ __forceinline__ uint32_t smem_u32(const void* p) {
    uint32_t a;
    asm("{ .reg .u64 t; cvta.to.shared.u64 t, %1; cvt.u32.u64 %0, t; }" : "=r"(a) : "l"(p));
    return a;
}
__device__ __forceinline__ void mma_tf32(float* c, const float* a, const float* b) {
    asm volatile(
        "mma.sync.aligned.m16n8k8.row.col.f32.tf32.tf32.f32 "
        "{%0,%1,%2,%3}, {%4,%5,%6,%7}, {%8,%9}, {%0,%1,%2,%3};"
        : "+f"(c[0]), "+f"(c[1]), "+f"(c[2]), "+f"(c[3])
        : "f"(a[0]), "f"(a[1]), "f"(a[2]), "f"(a[3]), "f"(b[0]), "f"(b[1]));
}
// exp(x) for x in [-80, 0] without MUFU: 2^(x*log2e), poly on [-0.5,0.5].
__device__ __forceinline__ float fexp_fma(float x) {
    float t = x * 1.4426950408889634f;
    float fn = rintf(t);
    float f = t - fn;
    float p = 1.5403530393381608e-4f;
    p = fmaf(p, f, 1.3333558146428443e-3f);
    p = fmaf(p, f, 9.6181291076284772e-3f);
    p = fmaf(p, f, 5.5504108664821580e-2f);
    p = fmaf(p, f, 2.4022650695910072e-1f);
    p = fmaf(p, f, 6.9314718055994531e-1f);
    p = fmaf(p, f, 1.0f);
    return __int_as_float(__float_as_int(p) + (((int)fn) << 23));
}

// ---------------- map: packed idx -> (a,b), a<=b ----------------
__global__ void map_kernel() {
    int a = threadIdx.x;
    int base = 64 * a - (a * (a - 1)) / 2;
    for (int b = a; b < AA; b++)
        g_map[base + (b - a)] = make_ushort2((unsigned short)a, (unsigned short)b);
}

// ---------------- Gpack in B-transposed-paired layout; 16 classes / block ----------------
__global__ void __launch_bounds__(256) prep_G_kernel(const float* __restrict__ W)
{
    __shared__ float sw[16][65];
    const int c0 = blockIdx.x * 16, tid = threadIdx.x;
    for (int idx = tid; idx < 16 * 64; idx += 256) {
        int ci = idx >> 6, a = idx & 63;
        sw[ci][a] = (c0 + ci < CC) ? W[(c0 + ci) * AA + a] : 0.f;
    }
    __syncthreads();
    if (tid < 16) {
        float s = 0.f;
        #pragma unroll
        for (int a = 0; a < AA; a++) s = fmaf(sw[tid][a], sw[tid][a], s);
        g_w2[c0 + tid] = s;
    }
    // rows: 67*16 = 1072 ; lanes: ci*2+sel
    const int lane = tid & 31, wrp = tid >> 5;
    const int ci = lane >> 1, sel = lane & 1;
    for (int row = wrp; row < KT * 16; row += 8) {
        int kt = row >> 4, rr = row & 15;
        int ks = rr >> 2, t = rr & 3;
        int l = kt * 32 + ks * 8 + t + 4 * sel;   // logical k
        float v;
        if (l < KTRI) { ushort2 ab = g_map[l]; v = sw[ci][ab.x] * sw[ci][ab.y]; }
        else          { v = sw[ci][l - KTRI]; }
        g_B[(size_t)row * 2048 + (c0 + ci) * 2 + sel] = tf32r(v);
    }
}

// ---------------- Apack (k-pair-permuted rows) + row consts ----------------
__global__ void __launch_bounds__(256) prep_A_kernel(
    const float* __restrict__ W, const int* __restrict__ tgt,
    const float* __restrict__ ratio_p, const float* __restrict__ CV)
{
    __shared__ float sM[AA * 65];
    __shared__ float swk[AA];
    __shared__ float su[AA];
    __shared__ float red[AA], red2[AA];
    const int n = blockIdx.x, tid = threadIdx.x;
    const int k = tgt[n];

    const float4* cv4 = reinterpret_cast<const float4*>(CV + (size_t)n * AA * AA);
    for (int i = 0; i < 4; i++) {
        int idx4 = tid + i * 256;
        float4 v = cv4[idx4];
        int row = idx4 >> 4, cc0 = (idx4 & 15) * 4;
        float* d = sM + row * 65 + cc0;
        d[0] = v.x; d[1] = v.y; d[2] = v.z; d[3] = v.w;
    }
    if (tid < AA) swk[tid] = W[k * AA + tid];
    __syncthreads();

    if (tid < AA) {
        const int a = tid;
        float trow = 0.f, tcol = 0.f;
        #pragma unroll 8
        for (int b = 0; b < AA; b++) {
            float wb = swk[b];
            trow = fmaf(sM[a * 65 + b], wb, trow);
            tcol = fmaf(sM[b * 65 + a], wb, tcol);
        }
        su[a]   = trow + tcol;
        red[a]  = swk[a] * trow;
        red2[a] = swk[a] * swk[a];
    }
    __syncthreads();
    for (int off = 32; off > 0; off >>= 1) {
        if (tid < off) { red[tid] += red[tid + off]; red2[tid] += red2[tid + off]; }
        __syncthreads();
    }
    if (tid == 0) g_rowconst[n] = fmaf(0.5f * ratio_p[0], red[0], -red2[0]);

    float* row = g_A + (size_t)n * KP;
    for (int t = tid; t < KP; t += 256) {
        // pos t holds logical k:  l = group + (t&1)*4 + ((t&7)>>1)
        int l = (t & ~7) + ((t & 1) * 4 + ((t & 7) >> 1));
        float v;
        if (l < KTRI) {
            ushort2 ab = g_map[l];
            v = (ab.x == ab.y) ? sM[ab.x * 65 + ab.x]
                               : sM[ab.x * 65 + ab.y] + sM[ab.y * 65 + ab.x];
        } else {
            v = -su[l - KTRI];
        }
        row[t] = tf32r(v);
    }
}

// ---------------- GEMM: 128 threads, 4 warps x (64x64), 2 CTAs/SM ----------------
__global__ void __launch_bounds__(128, 2) gemm_kernel(const float* __restrict__ ratio_p)
{
    extern __shared__ char smem[];
    const uint32_t sbase = smem_u32(smem);
    const int tid  = threadIdx.x;
    const int wid  = tid >> 5;
    const int lane = tid & 31;
    const int gid  = lane >> 2;
    const int tig  = lane & 3;
    const int m0 = blockIdx.x * BM;
    const int c0 = blockIdx.y * BN;
    const int wm0 = (wid >> 1) * 64;     // 0, 64
    const int wn0 = (wid & 1) * 64;      // 0, 64

    float acc[4][8][4];
    #pragma unroll
    for (int i = 0; i < 4; i++)
        #pragma unroll
        for (int j = 0; j < 8; j++)
            #pragma unroll
            for (int r = 0; r < 4; r++) acc[i][j][r] = 0.f;

    auto fill = [&](int s, int kt) {
        uint32_t bA = sbase + s * STAGE_B;
        uint32_t bB = bA + A_TILE_B;
        #pragma unroll
        for (int i = 0; i < 8; i++) {
            int ch = tid + i * 128;              // 0..1023
            int row = ch >> 3, cw = ch & 7;
            cpasync16(bA + row * (PA * 4) + cw * 16,
                      g_A + (size_t)(m0 + row) * KP + kt * BK + cw * 4);
        }
        #pragma unroll
        for (int i = 0; i < 8; i++) {
            int ch = tid + i * 128;              // 0..1023
            int r = ch >> 6, cw = ch & 63;
            cpasync16(bB + r * (PBR * 4) + cw * 16,
                      g_B + (size_t)kt * 32768 + r * 2048 + c0 * 2 + cw * 4);
        }
        asm volatile("cp.async.commit_group;\n" ::: "memory");
    };

    fill(0, 0);
    fill(1, 1);

    int s = 0;
    for (int kt = 0; kt < KT; kt++) {
        asm volatile("cp.async.wait_group 1;\n" ::: "memory");
        __syncthreads();
        if (kt + 2 < KT) {
            int s2 = s + 2; if (s2 >= 3) s2 -= 3;
            fill(s2, kt + 2);
        } else {
            asm volatile("cp.async.commit_group;\n" ::: "memory");
        }

        const float* sA = reinterpret_cast<const float*>(smem + s * STAGE_B);
        const float* sB = reinterpret_cast<const float*>(smem + s * STAGE_B + A_TILE_B);
        #pragma unroll
        for (int ks = 0; ks < 4; ks++) {
            float af[4][4];
            float bf[8][2];
            #pragma unroll
            for (int mt = 0; mt < 4; mt++) {
                int rb = wm0 + mt * 16 + gid;
                float2 lo = *reinterpret_cast<const float2*>(sA + rb * PA + ks * 8 + 2 * tig);
                float2 hi = *reinterpret_cast<const float2*>(sA + (rb + 8) * PA + ks * 8 + 2 * tig);
                af[mt][0] = lo.x; af[mt][1] = hi.x; af[mt][2] = lo.y; af[mt][3] = hi.y;
            }
            #pragma unroll
            for (int nt = 0; nt < 8; nt++) {
                int cb = wn0 + nt * 8 + gid;
                float2 bv = *reinterpret_cast<const float2*>(sB + (ks * 4 + tig) * PBR + cb * 2);
                bf[nt][0] = bv.x; bf[nt][1] = bv.y;
            }
            #pragma unroll
            for (int mt = 0; mt < 4; mt++)
                #pragma unroll
                for (int nt = 0; nt < 8; nt++)
                    mma_tf32(acc[mt][nt], af[mt], bf[nt]);
        }
        if (++s >= 3) s -= 3;
    }

    // epilogue: logits_partial = hr*acc + rowconst[r] + w2[c]
    const float hr = 0.5f * ratio_p[0];
    #pragma unroll
    for (int mt = 0; mt < 4; mt++) {
        int r0 = m0 + wm0 + mt * 16 + gid;
        int r1 = r0 + 8;
        float rc0 = g_rowconst[r0], rc1 = g_rowconst[r1];
        #pragma unroll
        for (int nt = 0; nt < 8; nt++) {
            int col = c0 + wn0 + nt * 8 + 2 * tig;
            if (col < CC) {
                float w20 = g_w2[col], w21 = g_w2[col + 1];
                float2 v0 = make_float2(fmaf(hr, acc[mt][nt][0], rc0 + w20),
                                        fmaf(hr, acc[mt][nt][1], rc0 + w21));
                float2 v1 = make_float2(fmaf(hr, acc[mt][nt][2], rc1 + w20),
                                        fmaf(hr, acc[mt][nt][3], rc1 + w21));
                *reinterpret_cast<float2*>(&g_logits[(size_t)r0 * CC + col]) = v0;
                *reinterpret_cast<float2*>(&g_logits[(size_t)r1 * CC + col]) = v1;
            }
        }
    }
}

// ---------------- softmax / NLL: warp per row, FMA-exp, no MUFU in hot path ----------------
__global__ void __launch_bounds__(256) softmax_kernel(
    const float* __restrict__ Y, const int* __restrict__ tgt)
{
    const int n = blockIdx.x * 8 + (threadIdx.x >> 5);
    const int lane = threadIdx.x & 31;
    const float* Lp = g_logits + (size_t)n * CC;
    const float* Yp = Y + (size_t)n * CC;
    const int k = tgt[n];

    float v[32];
    float lk = -1e30f;
    #pragma unroll
    for (int j = 0; j < 32; j++) {
        int i = lane + j * 32;
        bool ok = (i < CC);
        float val = ok ? (Lp[i] + Yp[i]) : -1e30f;
        v[j] = val;
        if (ok && i == k) lk = val;
    }
    float M = v[0];
    #pragma unroll
    for (int j = 1; j < 32; j++) M = fmaxf(M, v[j]);
    #pragma unroll
    for (int off = 16; off > 0; off >>= 1) {
        M = fmaxf(M, __shfl_xor_sync(0xffffffffu, M, off));
        lk = fmaxf(lk, __shfl_xor_sync(0xffffffffu, lk, off));
    }
    float s = 0.f;
    #pragma unroll
    for (int j = 0; j < 32; j++) s += fexp_fma(fmaxf(v[j] - M, -80.f));
    #pragma unroll
    for (int off = 16; off > 0; off >>= 1)
        s += __shfl_xor_sync(0xffffffffu, s, off);
    if (lane == 0) g_nll[n] = (M + logf(s)) - lk;
}

__global__ void __launch_bounds__(256) finalize_kernel(float* __restrict__ out)
{
    __shared__ float sh[256];
    float acc = 0.f;
    const float4* p = reinterpret_cast<const float4*>(g_nll);
    for (int i = threadIdx.x; i < NB / 4; i += 256) {
        float4 v = p[i];
        acc += (v.x + v.y) + (v.z + v.w);
    }
    sh[threadIdx.x] = acc;
    __syncthreads();
    #pragma unroll
    for (int off = 128; off > 0; off >>= 1) {
        if (threadIdx.x < off) sh[threadIdx.x] += sh[threadIdx.x + off];
        __syncthreads();
    }
    if (threadIdx.x == 0) out[0] = sh[0] * (1.0f / NB);
}

// ---------------- host ----------------
extern "C" void kernel_launch(void* const* d_in, const int* in_sizes, int n_in,
                              void* d_out, int out_size)
{
    const float* W     = (const float*)d_in[0];
    const float* Y     = (const float*)d_in[1];
    const int*   tgt   = (const int*)  d_in[3];
    const float* ratio = (const float*)d_in[4];
    const float* CV    = (const float*)d_in[5];
    float* out = (float*)d_out;

    cudaFuncSetAttribute(gemm_kernel, cudaFuncAttributeMaxDynamicSharedMemorySize, SMEM_TOTAL);

    map_kernel<<<1, 64>>>();
    prep_G_kernel<<<CPAD / 16, 256>>>(W);
    prep_A_kernel<<<NB, 256>>>(W, tgt, ratio, CV);
    gemm_kernel<<<dim3(NB / BM, CPAD / BN), 128, SMEM_TOTAL>>>(ratio);
    softmax_kernel<<<NB / 8, 256>>>(Y, tgt);
    finalize_kernel<<<1, 256>>>(out);

    if (out_size >= 1 + NB * CC) {
        cudaMemcpyAsync(out + 1, Y, (size_t)NB * CC * sizeof(float),
                        cudaMemcpyDeviceToDevice, 0);
    } else if (out_size == NB * CC) {
        cudaMemcpyAsync(out, Y, (size_t)NB * CC * sizeof(float),
                        cudaMemcpyDeviceToDevice, 0);
    }
}

// round 6
// speedup vs baseline: 8.3323x; 1.2053x over previous
#include <cuda_runtime.h>
#include <cuda_bf16.h>
#include <math.h>
#include <stdint.h>

// HFALoss: N=4096, C=1000 (pad 1024), A=64.
// d^T CV d = q_cc - w_c.u_n + r_n ; q via sym-packed GEMM (K1=2080) + cross tail (64).
// Q[4096x1024] = Apack @ Gpack^T in bf16 mma.sync m16n8k16; softmax fused into epilogue.
#define NB    4096
#define CC    1000
#define CPAD  1024
#define AA    64
#define KTRI  2080
#define KP    2144            // 67 * 32
#define KT    67
#define BM    128
#define BN    128
#define BK    32

#define A_TILE_B 8192         // [ks(2)][row(128)][32B perm bf16]
#define B_TILE_B 12288        // [col(128)][96B pitch: ks*32 + t*8, 64B data]
#define STAGE_B  (A_TILE_B + B_TILE_B)    // 20480
#define STAGES   4
#define SMEM_TOTAL (STAGES * STAGE_B)     // 81920

// ---------------- device scratch ----------------
__device__ __align__(128) __nv_bfloat16 g_A[(size_t)NB * KP];          // 17.6 MB
__device__ __align__(128) __nv_bfloat16 g_B[(size_t)KT * CPAD * 32];   //  4.4 MB
__device__ float  g_rowconst[NB];
__device__ float  g_w2[CPAD];
__device__ float  g_pmax[8 * NB];
__device__ float  g_psum[8 * NB];
__device__ float  g_lk[NB];
__device__ ushort2 g_map[KTRI];

__device__ __forceinline__ void cpasync16(uint32_t s, const void* g) {
    asm volatile("cp.async.cg.shared.global [%0], [%1], 16;\n" :: "r"(s), "l"(g));
}
__device__ __forceinline__ uint32_t smem_u32(const void* p) {
    uint32_t a;
    asm("{ .reg .u64 t; cvta.to.shared.u64 t, %1; cvt.u32.u64 %0, t; }" : "=r"(a) : "l"(p));
    return a;
}
__device__ __forceinline__ void mma_bf16(float* c, const uint32_t* a, const uint32_t* b) {
    asm volatile(
        "mma.sync.aligned.m16n8k16.row.col.f32.bf16.bf16.f32 "
        "{%0,%1,%2,%3}, {%4,%5,%6,%7}, {%8,%9}, {%0,%1,%2,%3};"
        : "+f"(c[0]), "+f"(c[1]), "+f"(c[2]), "+f"(c[3])
        : "r"(a[0]), "r"(a[1]), "r"(a[2]), "r"(a[3]), "r"(b[0]), "r"(b[1]));
}
// exp(x) for x in [-87, 0] without MUFU.
__device__ __forceinline__ float fexp_fma(float x) {
    float t = x * 1.4426950408889634f;
    float fn = rintf(t);
    float f = t - fn;
    float p = 1.5403530393381608e-4f;
    p = fmaf(p, f, 1.3333558146428443e-3f);
    p = fmaf(p, f, 9.6181291076284772e-3f);
    p = fmaf(p, f, 5.5504108664821580e-2f);
    p = fmaf(p, f, 2.4022650695910072e-1f);
    p = fmaf(p, f, 6.9314718055994531e-1f);
    p = fmaf(p, f, 1.0f);
    return __int_as_float(__float_as_int(p) + (((int)fn) << 23));
}
// position t (permuted storage) -> logical packed-k index
__device__ __forceinline__ int pos2logical(int t) {
    int j = t & 3, tt = (t >> 2) & 3;
    return (t & ~15) + 2 * tt + ((j >> 1) << 3) + (j & 1);
}

// ---------------- map: packed idx -> (a,b), a<=b ----------------
__global__ void map_kernel() {
    int a = threadIdx.x;
    int base = 64 * a - (a * (a - 1)) / 2;
    for (int b = a; b < AA; b++)
        g_map[base + (b - a)] = make_ushort2((unsigned short)a, (unsigned short)b);
}

// ---------------- Gpack -> g_B [kt][col][32 bf16 perm]; 16 classes / block ----------------
__global__ void __launch_bounds__(256) prep_G_kernel(const float* __restrict__ W)
{
    __shared__ float sw[16][65];
    const int c0 = blockIdx.x * 16, tid = threadIdx.x;
    for (int idx = tid; idx < 16 * 64; idx += 256) {
        int ci = idx >> 6, a = idx & 63;
        sw[ci][a] = (c0 + ci < CC) ? W[(c0 + ci) * AA + a] : 0.f;
    }
    __syncthreads();
    if (tid < 16) {
        float s = 0.f;
        #pragma unroll
        for (int a = 0; a < AA; a++) s = fmaf(sw[tid][a], sw[tid][a], s);
        g_w2[c0 + tid] = s;
    }
    for (int ci = 0; ci < 16; ci++) {
        const int c = c0 + ci;
        for (int t = tid; t < KP; t += 256) {
            int l = pos2logical(t);
            float v;
            if (l < KTRI) { ushort2 ab = g_map[l]; v = sw[ci][ab.x] * sw[ci][ab.y]; }
            else          { v = sw[ci][l - KTRI]; }
            int kt = t >> 5, p = t & 31;
            g_B[((size_t)kt * CPAD + c) * 32 + p] = __float2bfloat16(v);
        }
    }
}

// ---------------- Apack (permuted) + row consts ----------------
__global__ void __launch_bounds__(256) prep_A_kernel(
    const float* __restrict__ W, const int* __restrict__ tgt,
    const float* __restrict__ ratio_p, const float* __restrict__ CV)
{
    __shared__ float sM[AA * 65];
    __shared__ float swk[AA];
    __shared__ float su[AA];
    __shared__ float red[AA], red2[AA];
    const int n = blockIdx.x, tid = threadIdx.x;
    const int k = tgt[n];

    const float4* cv4 = reinterpret_cast<const float4*>(CV + (size_t)n * AA * AA);
    for (int i = 0; i < 4; i++) {
        int idx4 = tid + i * 256;
        float4 v = cv4[idx4];
        int row = idx4 >> 4, cc0 = (idx4 & 15) * 4;
        float* d = sM + row * 65 + cc0;
        d[0] = v.x; d[1] = v.y; d[2] = v.z; d[3] = v.w;
    }
    if (tid < AA) swk[tid] = W[k * AA + tid];
    __syncthreads();

    if (tid < AA) {
        const int a = tid;
        float trow = 0.f, tcol = 0.f;
        #pragma unroll 8
        for (int b = 0; b < AA; b++) {
            float wb = swk[b];
            trow = fmaf(sM[a * 65 + b], wb, trow);
            tcol = fmaf(sM[b * 65 + a], wb, tcol);
        }
        su[a]   = trow + tcol;
        red[a]  = swk[a] * trow;
        red2[a] = swk[a] * swk[a];
    }
    __syncthreads();
    for (int off = 32; off > 0; off >>= 1) {
        if (tid < off) { red[tid] += red[tid + off]; red2[tid] += red2[tid + off]; }
        __syncthreads();
    }
    if (tid == 0) g_rowconst[n] = fmaf(0.5f * ratio_p[0], red[0], -red2[0]);

    __nv_bfloat16* row = g_A + (size_t)n * KP;
    for (int t = tid; t < KP; t += 256) {
        int l = pos2logical(t);
        float v;
        if (l < KTRI) {
            ushort2 ab = g_map[l];
            v = (ab.x == ab.y) ? sM[ab.x * 65 + ab.x]
                               : sM[ab.x * 65 + ab.y] + sM[ab.y * 65 + ab.x];
        } else {
            v = -su[l - KTRI];
        }
        row[t] = __float2bfloat16(v);
    }
}

// ---------------- GEMM + fused softmax-partial epilogue ----------------
__global__ void __launch_bounds__(128, 2) gemm_kernel(
    const float* __restrict__ ratio_p, const float* __restrict__ Y,
    const int* __restrict__ tgt)
{
    extern __shared__ char smem[];
    const uint32_t sbase = smem_u32(smem);
    const int tid  = threadIdx.x;
    const int wid  = tid >> 5;
    const int lane = tid & 31;
    const int gid  = lane >> 2;
    const int tig  = lane & 3;
    const int m0 = blockIdx.x * BM;
    const int c0 = blockIdx.y * BN;
    const int wm0 = (wid >> 1) * 64;     // 0, 64
    const int wn0 = (wid & 1) * 64;      // 0, 64

    float acc[4][8][4];
    #pragma unroll
    for (int i = 0; i < 4; i++)
        #pragma unroll
        for (int j = 0; j < 8; j++)
            #pragma unroll
            for (int r = 0; r < 4; r++) acc[i][j][r] = 0.f;

    const char* gA = reinterpret_cast<const char*>(g_A);
    const char* gB = reinterpret_cast<const char*>(g_B);

    auto fill = [&](int s, int kt) {
        uint32_t bA = sbase + s * STAGE_B;
        uint32_t bB = bA + A_TILE_B;
        #pragma unroll
        for (int i = 0; i < 4; i++) {
            int ch = tid + i * 128;              // 0..511
            int row = ch >> 2, q = ch & 3;
            cpasync16(bA + (q >> 1) * 4096 + row * 32 + (q & 1) * 16,
                      gA + (size_t)(m0 + row) * (KP * 2) + kt * 64 + q * 16);
        }
        #pragma unroll
        for (int i = 0; i < 4; i++) {
            int ch = tid + i * 128;              // 0..511
            int col = ch >> 2, q = ch & 3;
            cpasync16(bB + col * 96 + q * 16,
                      gB + (size_t)kt * (CPAD * 64) + (size_t)(c0 + col) * 64 + q * 16);
        }
        asm volatile("cp.async.commit_group;\n" ::: "memory");
    };

    fill(0, 0); fill(1, 1); fill(2, 2);

    int s = 0;
    for (int kt = 0; kt < KT; kt++) {
        asm volatile("cp.async.wait_group 2;\n" ::: "memory");
        __syncthreads();
        if (kt + 3 < KT) fill((s + 3) & 3, kt + 3);
        else asm volatile("cp.async.commit_group;\n" ::: "memory");

        const char* sA = smem + s * STAGE_B;
        const char* sB = sA + A_TILE_B;
        #pragma unroll
        for (int ks = 0; ks < 2; ks++) {
            uint32_t af[4][4];
            uint32_t bf[8][2];
            #pragma unroll
            for (int mt = 0; mt < 4; mt++) {
                int rb = wm0 + mt * 16 + gid;
                uint2 lo = *reinterpret_cast<const uint2*>(sA + ks * 4096 + rb * 32 + tig * 8);
                uint2 hi = *reinterpret_cast<const uint2*>(sA + ks * 4096 + (rb + 8) * 32 + tig * 8);
                af[mt][0] = lo.x; af[mt][1] = hi.x; af[mt][2] = lo.y; af[mt][3] = hi.y;
            }
            #pragma unroll
            for (int nt = 0; nt < 8; nt++) {
                int cb = wn0 + nt * 8 + gid;
                uint2 bv = *reinterpret_cast<const uint2*>(sB + cb * 96 + ks * 32 + tig * 8);
                bf[nt][0] = bv.x; bf[nt][1] = bv.y;
            }
            #pragma unroll
            for (int mt = 0; mt < 4; mt++)
                #pragma unroll
                for (int nt = 0; nt < 8; nt++)
                    mma_bf16(acc[mt][nt], af[mt], bf[nt]);
        }
        s = (s + 1) & 3;
    }
    __syncthreads();   // mainloop smem dead; reuse for reductions

    // ---- fused epilogue: logits -> per-row (max, sumexp) partial + target logit ----
    float* sR = reinterpret_cast<float*>(smem);         // [4][64]
    float* sS = reinterpret_cast<float*>(smem) + 256;   // [4][64]
    const float hr = 0.5f * ratio_p[0];

    int   tcol[4][2];
    float rc[4][2];
    #pragma unroll
    for (int mt = 0; mt < 4; mt++)
        #pragma unroll
        for (int h = 0; h < 2; h++) {
            int rglob = m0 + wm0 + mt * 16 + gid + 8 * h;
            tcol[mt][h] = tgt[rglob];
            rc[mt][h] = g_rowconst[rglob];
        }

    float rmax[4][2];
    #pragma unroll
    for (int mt = 0; mt < 4; mt++) { rmax[mt][0] = -1e30f; rmax[mt][1] = -1e30f; }

    #pragma unroll
    for (int nt = 0; nt < 8; nt++) {
        int col = c0 + wn0 + nt * 8 + 2 * tig;
        bool ok0 = (col < CC), ok1 = (col + 1 < CC);
        float w20 = g_w2[col], w21 = g_w2[col + 1];
        #pragma unroll
        for (int mt = 0; mt < 4; mt++) {
            #pragma unroll
            for (int h = 0; h < 2; h++) {
                int rglob = m0 + wm0 + mt * 16 + gid + 8 * h;
                const float* Yr = Y + (size_t)rglob * CC;
                float y0 = ok0 ? Yr[col] : 0.f;
                float y1 = ok1 ? Yr[col + 1] : 0.f;
                float v0 = ok0 ? fmaf(hr, acc[mt][nt][2 * h + 0], rc[mt][h] + w20 + y0) : -1e30f;
                float v1 = ok1 ? fmaf(hr, acc[mt][nt][2 * h + 1], rc[mt][h] + w21 + y1) : -1e30f;
                if (col == tcol[mt][h])     g_lk[rglob] = v0;
                if (col + 1 == tcol[mt][h]) g_lk[rglob] = v1;
                acc[mt][nt][2 * h + 0] = v0;
                acc[mt][nt][2 * h + 1] = v1;
                rmax[mt][h] = fmaxf(rmax[mt][h], fmaxf(v0, v1));
            }
        }
    }
    // reduce max over tig lanes (same gid)
    #pragma unroll
    for (int mt = 0; mt < 4; mt++)
        #pragma unroll
        for (int h = 0; h < 2; h++) {
            rmax[mt][h] = fmaxf(rmax[mt][h], __shfl_xor_sync(0xffffffffu, rmax[mt][h], 1));
            rmax[mt][h] = fmaxf(rmax[mt][h], __shfl_xor_sync(0xffffffffu, rmax[mt][h], 2));
        }
    if (tig == 0) {
        #pragma unroll
        for (int mt = 0; mt < 4; mt++)
            #pragma unroll
            for (int h = 0; h < 2; h++)
                sR[wid * 64 + mt * 16 + gid + 8 * h] = rmax[mt][h];
    }
    __syncthreads();
    float Mf[4][2];
    #pragma unroll
    for (int mt = 0; mt < 4; mt++)
        #pragma unroll
        for (int h = 0; h < 2; h++) {
            int idx = mt * 16 + gid + 8 * h;
            Mf[mt][h] = fmaxf(sR[wid * 64 + idx], sR[(wid ^ 1) * 64 + idx]);
        }
    float rsum[4][2];
    #pragma unroll
    for (int mt = 0; mt < 4; mt++) { rsum[mt][0] = 0.f; rsum[mt][1] = 0.f; }
    #pragma unroll
    for (int nt = 0; nt < 8; nt++)
        #pragma unroll
        for (int mt = 0; mt < 4; mt++)
            #pragma unroll
            for (int h = 0; h < 2; h++) {
                rsum[mt][h] += fexp_fma(fmaxf(acc[mt][nt][2 * h + 0] - Mf[mt][h], -80.f));
                rsum[mt][h] += fexp_fma(fmaxf(acc[mt][nt][2 * h + 1] - Mf[mt][h], -80.f));
            }
    #pragma unroll
    for (int mt = 0; mt < 4; mt++)
        #pragma unroll
        for (int h = 0; h < 2; h++) {
            rsum[mt][h] += __shfl_xor_sync(0xffffffffu, rsum[mt][h], 1);
            rsum[mt][h] += __shfl_xor_sync(0xffffffffu, rsum[mt][h], 2);
        }
    __syncthreads();
    if (tig == 0) {
        #pragma unroll
        for (int mt = 0; mt < 4; mt++)
            #pragma unroll
            for (int h = 0; h < 2; h++)
                sS[wid * 64 + mt * 16 + gid + 8 * h] = rsum[mt][h];
    }
    __syncthreads();
    if (tig == 0 && (wid & 1) == 0) {
        const int ct = blockIdx.y;
        #pragma unroll
        for (int mt = 0; mt < 4; mt++)
            #pragma unroll
            for (int h = 0; h < 2; h++) {
                int idx = mt * 16 + gid + 8 * h;
                int rglob = m0 + wm0 + idx;
                g_pmax[ct * NB + rglob] = Mf[mt][h];
                g_psum[ct * NB + rglob] = sS[wid * 64 + idx] + sS[(wid ^ 1) * 64 + idx];
            }
    }
}

// ---------------- combine 8 partials per row -> nll -> mean ----------------
__global__ void __launch_bounds__(256) combine_finalize(float* __restrict__ out)
{
    __shared__ float sh[256];
    float acc = 0.f;
    for (int n = threadIdx.x; n < NB; n += 256) {
        float M = g_pmax[n];
        #pragma unroll
        for (int i = 1; i < 8; i++) M = fmaxf(M, g_pmax[i * NB + n]);
        float S = 0.f;
        #pragma unroll
        for (int i = 0; i < 8; i++)
            S += g_psum[i * NB + n] * fexp_fma(fmaxf(g_pmax[i * NB + n] - M, -80.f));
        acc += (M + logf(S)) - g_lk[n];
    }
    sh[threadIdx.x] = acc;
    __syncthreads();
    #pragma unroll
    for (int off = 128; off > 0; off >>= 1) {
        if (threadIdx.x < off) sh[threadIdx.x] += sh[threadIdx.x + off];
        __syncthreads();
    }
    if (threadIdx.x == 0) out[0] = sh[0] * (1.0f / NB);
}

// ---------------- host ----------------
extern "C" void kernel_launch(void* const* d_in, const int* in_sizes, int n_in,
                              void* d_out, int out_size)
{
    const float* W     = (const float*)d_in[0];
    const float* Y     = (const float*)d_in[1];
    const int*   tgt   = (const int*)  d_in[3];
    const float* ratio = (const float*)d_in[4];
    const float* CV    = (const float*)d_in[5];
    float* out = (float*)d_out;

    cudaFuncSetAttribute(gemm_kernel, cudaFuncAttributeMaxDynamicSharedMemorySize, SMEM_TOTAL);

    map_kernel<<<1, 64>>>();
    prep_G_kernel<<<CPAD / 16, 256>>>(W);
    prep_A_kernel<<<NB, 256>>>(W, tgt, ratio, CV);
    gemm_kernel<<<dim3(NB / BM, CPAD / BN), 128, SMEM_TOTAL>>>(ratio, Y, tgt);
    combine_finalize<<<1, 256>>>(out);

    if (out_size >= 1 + NB * CC) {
        cudaMemcpyAsync(out + 1, Y, (size_t)NB * CC * sizeof(float),
                        cudaMemcpyDeviceToDevice, 0);
    } else if (out_size == NB * CC) {
        cudaMemcpyAsync(out, Y, (size_t)NB * CC * sizeof(float),
                        cudaMemcpyDeviceToDevice, 0);
    }
}

// round 7
// speedup vs baseline: 9.1918x; 1.1032x over previous
#include <cuda_runtime.h>
#include <cuda_bf16.h>
#include <math.h>
#include <stdint.h>

// HFALoss: N=4096, C=1000 (pad 1024), A=64.
// d^T CV d = q_cc - w_c.u_n + r_n ; q via sym-packed GEMM (K1=2080) + cross tail (64).
// Q[4096x1024] = Apack @ Gpack^T in bf16 mma.sync m16n8k16; softmax fused into epilogue.
#define NB    4096
#define CC    1000
#define CPAD  1024
#define AA    64
#define KTRI  2080
#define KP    2144            // 67 * 32
#define KT    67
#define BM    128
#define BN    128

#define A_TILE_B 8192         // [ks(2)][row(128)][32B perm bf16]
#define B_TILE_B 12288        // [col(128)][96B pitch: ks*32 + t*8, 64B data]
#define STAGE_B  (A_TILE_B + B_TILE_B)    // 20480
#define SMEM_TOTAL (4 * STAGE_B)          // 81920

// ---------------- device scratch ----------------
__device__ __align__(128) __nv_bfloat16 g_A[(size_t)NB * KP];          // 17.6 MB
__device__ __align__(128) __nv_bfloat16 g_B[(size_t)KT * CPAD * 32];   //  4.4 MB
__device__ float  g_rowconst[NB];
__device__ float  g_w2[CPAD];
__device__ float  g_pmax[8 * NB];
__device__ float  g_psum[8 * NB];
__device__ float  g_lk[NB];
__device__ ushort2 g_map[KTRI];

__device__ __forceinline__ void cpasync16(uint32_t s, const void* g) {
    asm volatile("cp.async.cg.shared.global [%0], [%1], 16;\n" :: "r"(s), "l"(g));
}
__device__ __forceinline__ uint32_t smem_u32(const void* p) {
    uint32_t a;
    asm("{ .reg .u64 t; cvta.to.shared.u64 t, %1; cvt.u32.u64 %0, t; }" : "=r"(a) : "l"(p));
    return a;
}
__device__ __forceinline__ void mma_bf16(float* c, const uint32_t* a, const uint32_t* b) {
    asm volatile(
        "mma.sync.aligned.m16n8k16.row.col.f32.bf16.bf16.f32 "
        "{%0,%1,%2,%3}, {%4,%5,%6,%7}, {%8,%9}, {%0,%1,%2,%3};"
        : "+f"(c[0]), "+f"(c[1]), "+f"(c[2]), "+f"(c[3])
        : "r"(a[0]), "r"(a[1]), "r"(a[2]), "r"(a[3]), "r"(b[0]), "r"(b[1]));
}
// exp(x) for x in [-87, 0] without MUFU.
__device__ __forceinline__ float fexp_fma(float x) {
    float t = x * 1.4426950408889634f;
    float fn = rintf(t);
    float f = t - fn;
    float p = 1.5403530393381608e-4f;
    p = fmaf(p, f, 1.3333558146428443e-3f);
    p = fmaf(p, f, 9.6181291076284772e-3f);
    p = fmaf(p, f, 5.5504108664821580e-2f);
    p = fmaf(p, f, 2.4022650695910072e-1f);
    p = fmaf(p, f, 6.9314718055994531e-1f);
    p = fmaf(p, f, 1.0f);
    return __int_as_float(__float_as_int(p) + (((int)fn) << 23));
}
// position t (permuted storage) -> logical packed-k index.
// even t -> even intra-quad j in {0,2}: l(t) and l(t)+1 = l(t+1) pair up.
__device__ __forceinline__ int pos2logical(int t) {
    int j = t & 3, tt = (t >> 2) & 3;
    return (t & ~15) + 2 * tt + ((j >> 1) << 3) + (j & 1);
}

// ---------------- map: packed idx -> (a,b), a<=b ----------------
__global__ void map_kernel() {
    int a = threadIdx.x;
    int base = 64 * a - (a * (a - 1)) / 2;
    for (int b = a; b < AA; b++)
        g_map[base + (b - a)] = make_ushort2((unsigned short)a, (unsigned short)b);
}

// ---------------- Gpack -> g_B [kt][col][32 bf16 perm]; 16 classes / block ----------------
__global__ void __launch_bounds__(256) prep_G_kernel(const float* __restrict__ W)
{
    __shared__ float sw[16][65];
    const int c0 = blockIdx.x * 16, tid = threadIdx.x;
    for (int idx = tid; idx < 16 * 64; idx += 256) {
        int ci = idx >> 6, a = idx & 63;
        sw[ci][a] = (c0 + ci < CC) ? W[(c0 + ci) * AA + a] : 0.f;
    }
    __syncthreads();
    if (tid < 16) {
        float s = 0.f;
        #pragma unroll
        for (int a = 0; a < AA; a++) s = fmaf(sw[tid][a], sw[tid][a], s);
        g_w2[c0 + tid] = s;
    }
    uint32_t* gB32 = reinterpret_cast<uint32_t*>(g_B);
    for (int ci = 0; ci < 16; ci++) {
        const int c = c0 + ci;
        for (int t2 = tid; t2 < KP / 2; t2 += 256) {
            int t = 2 * t2;
            int l = pos2logical(t);         // even; pair is l, l+1
            float v0, v1;
            if (l < KTRI) {
                ushort2 ab0 = g_map[l], ab1 = g_map[l + 1];
                v0 = sw[ci][ab0.x] * sw[ci][ab0.y];
                v1 = sw[ci][ab1.x] * sw[ci][ab1.y];
            } else {
                v0 = sw[ci][l - KTRI];
                v1 = sw[ci][l + 1 - KTRI];
            }
            __nv_bfloat162 h = __floats2bfloat162_rn(v0, v1);
            int kt = t >> 5, p = t & 31;
            gB32[((size_t)kt * CPAD + c) * 16 + (p >> 1)] = *reinterpret_cast<uint32_t*>(&h);
        }
    }
}

// ---------------- Apack (permuted, paired stores) + row consts ----------------
__global__ void __launch_bounds__(256) prep_A_kernel(
    const float* __restrict__ W, const int* __restrict__ tgt,
    const float* __restrict__ ratio_p, const float* __restrict__ CV)
{
    __shared__ float sM[AA * 65];
    __shared__ float swk[AA];
    __shared__ float su[AA];
    __shared__ float pr[4][AA], pc[4][AA];
    __shared__ float red[AA], red2[AA];
    const int n = blockIdx.x, tid = threadIdx.x;
    const int k = tgt[n];

    const float4* cv4 = reinterpret_cast<const float4*>(CV + (size_t)n * AA * AA);
    #pragma unroll
    for (int i = 0; i < 4; i++) {
        int idx4 = tid + i * 256;
        float4 v = cv4[idx4];
        int row = idx4 >> 4, cc0 = (idx4 & 15) * 4;
        float* d = sM + row * 65 + cc0;
        d[0] = v.x; d[1] = v.y; d[2] = v.z; d[3] = v.w;
    }
    if (tid < AA) swk[tid] = W[k * AA + tid];
    __syncthreads();

    {   // u partials: all 256 threads (a = tid&63, quarter of b-range each)
        int a = tid & 63, part = tid >> 6;
        float tr = 0.f, tc = 0.f;
        int b0 = part * 16;
        #pragma unroll
        for (int j = 0; j < 16; j++) {
            int b = b0 + j;
            float wb = swk[b];
            tr = fmaf(sM[a * 65 + b], wb, tr);
            tc = fmaf(sM[b * 65 + a], wb, tc);
        }
        pr[part][a] = tr; pc[part][a] = tc;
    }
    __syncthreads();
    if (tid < AA) {
        float trow = pr[0][tid] + pr[1][tid] + pr[2][tid] + pr[3][tid];
        float tcol = pc[0][tid] + pc[1][tid] + pc[2][tid] + pc[3][tid];
        su[tid]   = trow + tcol;
        red[tid]  = swk[tid] * trow;
        red2[tid] = swk[tid] * swk[tid];
    }
    __syncthreads();
    if (tid < 32) {
        float r  = red[tid] + red[tid + 32];
        float r2 = red2[tid] + red2[tid + 32];
        #pragma unroll
        for (int off = 16; off > 0; off >>= 1) {
            r  += __shfl_xor_sync(0xffffffffu, r, off);
            r2 += __shfl_xor_sync(0xffffffffu, r2, off);
        }
        if (tid == 0) g_rowconst[n] = fmaf(0.5f * ratio_p[0], r, -r2);
    }

    uint32_t* row32 = reinterpret_cast<uint32_t*>(g_A + (size_t)n * KP);
    for (int t2 = tid; t2 < KP / 2; t2 += 256) {
        int t = 2 * t2;
        int l = pos2logical(t);
        float v0, v1;
        if (l < KTRI) {
            ushort2 ab0 = g_map[l], ab1 = g_map[l + 1];
            v0 = (ab0.x == ab0.y) ? sM[ab0.x * 65 + ab0.x]
                                  : sM[ab0.x * 65 + ab0.y] + sM[ab0.y * 65 + ab0.x];
            v1 = (ab1.x == ab1.y) ? sM[ab1.x * 65 + ab1.x]
                                  : sM[ab1.x * 65 + ab1.y] + sM[ab1.y * 65 + ab1.x];
        } else {
            v0 = -su[l - KTRI];
            v1 = -su[l + 1 - KTRI];
        }
        __nv_bfloat162 h = __floats2bfloat162_rn(v0, v1);
        row32[t2] = *reinterpret_cast<uint32_t*>(&h);
    }
}

// ---------------- GEMM (256 thr, 8 warps x 64x32) + fused softmax epilogue ----------------
__global__ void __launch_bounds__(256, 2) gemm_kernel(
    const float* __restrict__ ratio_p, const float* __restrict__ Y,
    const int* __restrict__ tgt)
{
    extern __shared__ char smem[];
    const uint32_t sbase = smem_u32(smem);
    const int tid  = threadIdx.x;
    const int wid  = tid >> 5;
    const int lane = tid & 31;
    const int gid  = lane >> 2;
    const int tig  = lane & 3;
    const int m0 = blockIdx.x * BM;
    const int c0 = blockIdx.y * BN;
    const int wm0 = (wid >> 2) * 64;     // 0, 64
    const int wn0 = (wid & 3) * 32;      // 0,32,64,96

    float acc[4][4][4];
    #pragma unroll
    for (int i = 0; i < 4; i++)
        #pragma unroll
        for (int j = 0; j < 4; j++)
            #pragma unroll
            for (int r = 0; r < 4; r++) acc[i][j][r] = 0.f;

    const char* gA = reinterpret_cast<const char*>(g_A);
    const char* gB = reinterpret_cast<const char*>(g_B);

    auto fill = [&](int s, int kt) {
        uint32_t bA = sbase + s * STAGE_B;
        uint32_t bB = bA + A_TILE_B;
        #pragma unroll
        for (int i = 0; i < 2; i++) {
            int ch = tid + i * 256;              // 0..511
            int row = ch >> 2, q = ch & 3;
            cpasync16(bA + (q >> 1) * 4096 + row * 32 + (q & 1) * 16,
                      gA + (size_t)(m0 + row) * (KP * 2) + kt * 64 + q * 16);
        }
        #pragma unroll
        for (int i = 0; i < 2; i++) {
            int ch = tid + i * 256;              // 0..511
            int col = ch >> 2, q = ch & 3;
            cpasync16(bB + col * 96 + q * 16,
                      gB + (size_t)kt * (CPAD * 64) + (size_t)(c0 + col) * 64 + q * 16);
        }
        asm volatile("cp.async.commit_group;\n" ::: "memory");
    };

    fill(0, 0); fill(1, 1); fill(2, 2);

    int s = 0;
    for (int kt = 0; kt < KT; kt++) {
        asm volatile("cp.async.wait_group 2;\n" ::: "memory");
        __syncthreads();
        if (kt + 3 < KT) fill((s + 3) & 3, kt + 3);
        else asm volatile("cp.async.commit_group;\n" ::: "memory");

        const char* sA = smem + s * STAGE_B;
        const char* sB = sA + A_TILE_B;
        #pragma unroll
        for (int ks = 0; ks < 2; ks++) {
            uint32_t af[4][4];
            uint32_t bf[4][2];
            #pragma unroll
            for (int mt = 0; mt < 4; mt++) {
                int rb = wm0 + mt * 16 + gid;
                uint2 lo = *reinterpret_cast<const uint2*>(sA + ks * 4096 + rb * 32 + tig * 8);
                uint2 hi = *reinterpret_cast<const uint2*>(sA + ks * 4096 + (rb + 8) * 32 + tig * 8);
                af[mt][0] = lo.x; af[mt][1] = hi.x; af[mt][2] = lo.y; af[mt][3] = hi.y;
            }
            #pragma unroll
            for (int nt = 0; nt < 4; nt++) {
                int cb = wn0 + nt * 8 + gid;
                uint2 bv = *reinterpret_cast<const uint2*>(sB + cb * 96 + ks * 32 + tig * 8);
                bf[nt][0] = bv.x; bf[nt][1] = bv.y;
            }
            #pragma unroll
            for (int mt = 0; mt < 4; mt++)
                #pragma unroll
                for (int nt = 0; nt < 4; nt++)
                    mma_bf16(acc[mt][nt], af[mt], bf[nt]);
        }
        s = (s + 1) & 3;
    }
    __syncthreads();   // mainloop smem dead; reuse for reductions

    // ---- fused epilogue: per-row (max, sumexp) partial + target logit ----
    float* sR = reinterpret_cast<float*>(smem);         // [8][64]
    float* sS = reinterpret_cast<float*>(smem) + 512;   // [8][64]
    const float hr = 0.5f * ratio_p[0];

    int   tcol[4][2];
    float rc[4][2];
    #pragma unroll
    for (int mt = 0; mt < 4; mt++)
        #pragma unroll
        for (int h = 0; h < 2; h++) {
            int rglob = m0 + wm0 + mt * 16 + gid + 8 * h;
            tcol[mt][h] = tgt[rglob];
            rc[mt][h] = g_rowconst[rglob];
        }

    float rmax[4][2];
    #pragma unroll
    for (int mt = 0; mt < 4; mt++) { rmax[mt][0] = -1e30f; rmax[mt][1] = -1e30f; }

    #pragma unroll
    for (int nt = 0; nt < 4; nt++) {
        int col = c0 + wn0 + nt * 8 + 2 * tig;
        bool ok0 = (col < CC), ok1 = (col + 1 < CC);
        float w20 = g_w2[col], w21 = g_w2[col + 1];
        #pragma unroll
        for (int mt = 0; mt < 4; mt++) {
            #pragma unroll
            for (int h = 0; h < 2; h++) {
                int rglob = m0 + wm0 + mt * 16 + gid + 8 * h;
                const float* Yr = Y + (size_t)rglob * CC;
                float y0 = ok0 ? Yr[col] : 0.f;
                float y1 = ok1 ? Yr[col + 1] : 0.f;
                float v0 = ok0 ? fmaf(hr, acc[mt][nt][2 * h + 0], rc[mt][h] + w20 + y0) : -1e30f;
                float v1 = ok1 ? fmaf(hr, acc[mt][nt][2 * h + 1], rc[mt][h] + w21 + y1) : -1e30f;
                if (col == tcol[mt][h])     g_lk[rglob] = v0;
                if (col + 1 == tcol[mt][h]) g_lk[rglob] = v1;
                acc[mt][nt][2 * h + 0] = v0;
                acc[mt][nt][2 * h + 1] = v1;
                rmax[mt][h] = fmaxf(rmax[mt][h], fmaxf(v0, v1));
            }
        }
    }
    #pragma unroll
    for (int mt = 0; mt < 4; mt++)
        #pragma unroll
        for (int h = 0; h < 2; h++) {
            rmax[mt][h] = fmaxf(rmax[mt][h], __shfl_xor_sync(0xffffffffu, rmax[mt][h], 1));
            rmax[mt][h] = fmaxf(rmax[mt][h], __shfl_xor_sync(0xffffffffu, rmax[mt][h], 2));
        }
    if (tig == 0) {
        #pragma unroll
        for (int mt = 0; mt < 4; mt++)
            #pragma unroll
            for (int h = 0; h < 2; h++)
                sR[wid * 64 + mt * 16 + gid + 8 * h] = rmax[mt][h];
    }
    __syncthreads();
    const int wg4 = (wid >> 2) * 4;      // warp group base sharing my rows
    float Mf[4][2];
    #pragma unroll
    for (int mt = 0; mt < 4; mt++)
        #pragma unroll
        for (int h = 0; h < 2; h++) {
            int idx = mt * 16 + gid + 8 * h;
            float mv = sR[wg4 * 64 + idx];
            mv = fmaxf(mv, sR[(wg4 + 1) * 64 + idx]);
            mv = fmaxf(mv, sR[(wg4 + 2) * 64 + idx]);
            mv = fmaxf(mv, sR[(wg4 + 3) * 64 + idx]);
            Mf[mt][h] = mv;
        }
    float rsum[4][2];
    #pragma unroll
    for (int mt = 0; mt < 4; mt++) { rsum[mt][0] = 0.f; rsum[mt][1] = 0.f; }
    #pragma unroll
    for (int nt = 0; nt < 4; nt++)
        #pragma unroll
        for (int mt = 0; mt < 4; mt++)
            #pragma unroll
            for (int h = 0; h < 2; h++) {
                rsum[mt][h] += fexp_fma(fmaxf(acc[mt][nt][2 * h + 0] - Mf[mt][h], -80.f));
                rsum[mt][h] += fexp_fma(fmaxf(acc[mt][nt][2 * h + 1] - Mf[mt][h], -80.f));
            }
    #pragma unroll
    for (int mt = 0; mt < 4; mt++)
        #pragma unroll
        for (int h = 0; h < 2; h++) {
            rsum[mt][h] += __shfl_xor_sync(0xffffffffu, rsum[mt][h], 1);
            rsum[mt][h] += __shfl_xor_sync(0xffffffffu, rsum[mt][h], 2);
        }
    __syncthreads();
    if (tig == 0) {
        #pragma unroll
        for (int mt = 0; mt < 4; mt++)
            #pragma unroll
            for (int h = 0; h < 2; h++)
                sS[wid * 64 + mt * 16 + gid + 8 * h] = rsum[mt][h];
    }
    __syncthreads();
    if (tig == 0 && (wid & 3) == 0) {
        const int ct = blockIdx.y;
        #pragma unroll
        for (int mt = 0; mt < 4; mt++)
            #pragma unroll
            for (int h = 0; h < 2; h++) {
                int idx = mt * 16 + gid + 8 * h;
                int rglob = m0 + wm0 + idx;
                float ssum = sS[wg4 * 64 + idx] + sS[(wg4 + 1) * 64 + idx]
                           + sS[(wg4 + 2) * 64 + idx] + sS[(wg4 + 3) * 64 + idx];
                g_pmax[ct * NB + rglob] = Mf[mt][h];
                g_psum[ct * NB + rglob] = ssum;
            }
    }
}

// ---------------- combine 8 partials per row -> nll -> mean ----------------
__global__ void __launch_bounds__(256) combine_finalize(float* __restrict__ out)
{
    __shared__ float sh[256];
    float acc = 0.f;
    for (int n = threadIdx.x; n < NB; n += 256) {
        float M = g_pmax[n];
        #pragma unroll
        for (int i = 1; i < 8; i++) M = fmaxf(M, g_pmax[i * NB + n]);
        float S = 0.f;
        #pragma unroll
        for (int i = 0; i < 8; i++)
            S += g_psum[i * NB + n] * fexp_fma(fmaxf(g_pmax[i * NB + n] - M, -80.f));
        acc += (M + logf(S)) - g_lk[n];
    }
    sh[threadIdx.x] = acc;
    __syncthreads();
    #pragma unroll
    for (int off = 128; off > 0; off >>= 1) {
        if (threadIdx.x < off) sh[threadIdx.x] += sh[threadIdx.x + off];
        __syncthreads();
    }
    if (threadIdx.x == 0) out[0] = sh[0] * (1.0f / NB);
}

// ---------------- host ----------------
extern "C" void kernel_launch(void* const* d_in, const int* in_sizes, int n_in,
                              void* d_out, int out_size)
{
    const float* W     = (const float*)d_in[0];
    const float* Y     = (const float*)d_in[1];
    const int*   tgt   = (const int*)  d_in[3];
    const float* ratio = (const float*)d_in[4];
    const float* CV    = (const float*)d_in[5];
    float* out = (float*)d_out;

    cudaFuncSetAttribute(gemm_kernel, cudaFuncAttributeMaxDynamicSharedMemorySize, SMEM_TOTAL);

    map_kernel<<<1, 64>>>();
    prep_G_kernel<<<CPAD / 16, 256>>>(W);
    prep_A_kernel<<<NB, 256>>>(W, tgt, ratio, CV);
    gemm_kernel<<<dim3(NB / BM, CPAD / BN), 256, SMEM_TOTAL>>>(ratio, Y, tgt);
    combine_finalize<<<1, 256>>>(out);

    if (out_size >= 1 + NB * CC) {
        cudaMemcpyAsync(out + 1, Y, (size_t)NB * CC * sizeof(float),
                        cudaMemcpyDeviceToDevice, 0);
    } else if (out_size == NB * CC) {
        cudaMemcpyAsync(out, Y, (size_t)NB * CC * sizeof(float),
                        cudaMemcpyDeviceToDevice, 0);
    }
}